// round 16
// baseline (speedup 1.0000x reference)
#include <cuda_runtime.h>
#include <cuda_fp16.h>
#include <cstdint>

#define DI __device__ __forceinline__

// Problem sizes (fixed for this dataset)
constexpr int Bc = 2, Tc = 2048, Cc = 1024, Hc = 16, Dc = 64;
constexpr int Mrows = Bc * Tc;      // 4096
constexpr int BHc = Bc * Hc;        // 32
constexpr int Kdim = 1024;

// ---------------- static device scratch (no allocs allowed) ----------------
__device__ __align__(128) __half g_xh[Mrows * Cc];
__device__ __align__(128) __half g_wq[Cc * Cc], g_wk[Cc * Cc], g_wv[Cc * Cc], g_wo[Cc * Cc];
__device__ __align__(128) __half g_q[BHc * Tc * Dc], g_k[BHc * Tc * Dc], g_v[BHc * Tc * Dc];
__device__ __align__(128) __half g_attn[Mrows * Cc];

DI __half* sel_buf(int s) {
    switch (s) {
        case 0: return g_xh;
        case 1: return g_wq;
        case 2: return g_wk;
        case 3: return g_wv;
        case 4: return g_wo;
        case 5: return g_q;
        case 6: return g_k;
        case 7: return g_v;
        default: return g_attn;
    }
}

// ---------------- fused fp32 -> fp16 conversion, 4 float4/thread --------------
__global__ void k_cvt_all(const float* __restrict__ x, const float* __restrict__ wq,
                          const float* __restrict__ wk, const float* __restrict__ wv,
                          const float* __restrict__ wo) {
    int bid = blockIdx.x;
    const float* src;
    __half* dst;
    int base;
    if (bid < 1024) {
        src = x; dst = g_xh; base = bid * 1024;
    } else {
        int w = (bid - 1024) >> 8;            // 256 blocks per weight
        int lb = (bid - 1024) & 255;
        switch (w) {
            case 0: src = wq; dst = g_wq; break;
            case 1: src = wk; dst = g_wk; break;
            case 2: src = wv; dst = g_wv; break;
            default: src = wo; dst = g_wo; break;
        }
        base = lb * 1024;
    }
    float4 v[4];
#pragma unroll
    for (int j = 0; j < 4; j++)
        v[j] = reinterpret_cast<const float4*>(src)[base + threadIdx.x + j * 256];
#pragma unroll
    for (int j = 0; j < 4; j++) {
        __half2 h0 = __floats2half2_rn(v[j].x, v[j].y);
        __half2 h1 = __floats2half2_rn(v[j].z, v[j].w);
        uint2 pk;
        pk.x = *reinterpret_cast<uint32_t*>(&h0);
        pk.y = *reinterpret_cast<uint32_t*>(&h1);
        reinterpret_cast<uint2*>(dst)[base + threadIdx.x + j * 256] = pk;
    }
}

// ---------------- PTX helpers ----------------
DI uint32_t smem_u32(const void* p) {
    uint32_t a;
    asm("{ .reg .u64 t; cvta.to.shared.u64 t, %1; cvt.u32.u64 %0, t; }" : "=r"(a) : "l"(p));
    return a;
}
DI void cp_async16(uint32_t dst, const void* src) {
    asm volatile("cp.async.cg.shared.global [%0], [%1], 16;" :: "r"(dst), "l"(src) : "memory");
}
DI void cp_commit() { asm volatile("cp.async.commit_group;" ::: "memory"); }
template <int N> DI void cp_wait() { asm volatile("cp.async.wait_group %0;" :: "n"(N) : "memory"); }

DI void mma_16816(float* d, const uint32_t* a, uint32_t b0, uint32_t b1) {
    asm volatile(
        "mma.sync.aligned.m16n8k16.row.col.f32.f16.f16.f32 "
        "{%0,%1,%2,%3}, {%4,%5,%6,%7}, {%8,%9}, {%0,%1,%2,%3};\n"
        : "+f"(d[0]), "+f"(d[1]), "+f"(d[2]), "+f"(d[3])
        : "r"(a[0]), "r"(a[1]), "r"(a[2]), "r"(a[3]), "r"(b0), "r"(b1));
}
DI void ldsm_x4(uint32_t* r, uint32_t a) {
    asm volatile("ldmatrix.sync.aligned.m8n8.x4.shared.b16 {%0,%1,%2,%3}, [%4];"
                 : "=r"(r[0]), "=r"(r[1]), "=r"(r[2]), "=r"(r[3]) : "r"(a));
}
DI void ldsm_x4_t(uint32_t* r, uint32_t a) {
    asm volatile("ldmatrix.sync.aligned.m8n8.x4.trans.shared.b16 {%0,%1,%2,%3}, [%4];"
                 : "=r"(r[0]), "=r"(r[1]), "=r"(r[2]), "=r"(r[3]) : "r"(a));
}

// ---------------- GEMM v4 (frozen mainloop): 128x128 CTA, K-chunk 64, 3-stage -
// EPI=0 epilogue change: Q output (blockIdx.z==0) is pre-scaled by 0.125 (=2^-3,
// exact in fp16) so attention can drop its per-element scale multiply.
constexpr uint32_t GSTG = 36864;
constexpr uint32_t GEMM_SMEM = 3 * GSTG;   // 110592

template <int EPI>
__global__ __launch_bounds__(256, 2) void k_gemm(float* __restrict__ outF) {
    extern __shared__ __align__(128) char smem[];
    const uint32_t sb = smem_u32(smem);

    const __half* A = (EPI == 0 ? g_xh : g_attn) + (size_t)blockIdx.y * 128 * Kdim;
    const __half* Bm = (EPI == 0 ? sel_buf(1 + blockIdx.z) : g_wo) + (size_t)blockIdx.x * 128 * Kdim;

    const int tid = threadIdx.x;
    const int lane = tid & 31, warp = tid >> 5;
    const int wm = warp >> 1, wn = warp & 1;
    const int r = lane >> 2, cq = lane & 3;
    const int g = lane >> 3;
    const uint32_t off16 = (uint32_t)(((g & 1) * 8 + (lane & 7)) * 144 + (g >> 1) * 16);

    const int lrow = tid >> 3, lc = tid & 7;

    float acc[2][8][4];
#pragma unroll
    for (int mi = 0; mi < 2; mi++)
#pragma unroll
        for (int ni = 0; ni < 8; ni++)
#pragma unroll
            for (int e = 0; e < 4; e++) acc[mi][ni][e] = 0.f;

#define LOAD_STAGE(KT_, ST_)                                                            \
    {                                                                                   \
        const int kt_ = (KT_);                                                          \
        const uint32_t sA = sb + (uint32_t)(ST_) * GSTG;                                \
        const uint32_t sB = sA + 18432;                                                 \
        _Pragma("unroll")                                                               \
        for (int i_ = 0; i_ < 4; i_++) {                                                \
            int row_ = lrow + i_ * 32;                                                  \
            cp_async16(sA + row_ * 144 + lc * 16, A + (size_t)row_ * Kdim + kt_ * 64 + lc * 8);  \
        }                                                                               \
        _Pragma("unroll")                                                               \
        for (int i_ = 0; i_ < 4; i_++) {                                                \
            int row_ = lrow + i_ * 32;                                                  \
            cp_async16(sB + row_ * 144 + lc * 16, Bm + (size_t)row_ * Kdim + kt_ * 64 + lc * 8); \
        }                                                                               \
    }

    LOAD_STAGE(0, 0); cp_commit();
    LOAD_STAGE(1, 1); cp_commit();

    constexpr int KT = Kdim / 64;   // 16
    int stC = 0;
    for (int kt = 0; kt < KT; kt++) {
        cp_wait<1>();
        __syncthreads();
        int stL = stC + 2; if (stL >= 3) stL -= 3;
        if (kt + 2 < KT) LOAD_STAGE(kt + 2, stL);
        cp_commit();

        const uint32_t sA = sb + (uint32_t)stC * GSTG;
        const uint32_t sB = sA + 18432;
#pragma unroll
        for (int kk = 0; kk < 4; kk++) {
            uint32_t a0[4], a1[4];
            ldsm_x4(a0, sA + (uint32_t)((wm * 32) * 144 + kk * 32) + off16);
            ldsm_x4(a1, sA + (uint32_t)((wm * 32 + 16) * 144 + kk * 32) + off16);
#pragma unroll
            for (int nq = 0; nq < 4; nq++) {
                uint32_t b[4];
                ldsm_x4(b, sB + (uint32_t)((wn * 64 + nq * 16) * 144 + kk * 32) + off16);
                mma_16816(acc[0][2 * nq],     a0, b[0], b[2]);
                mma_16816(acc[0][2 * nq + 1], a0, b[1], b[3]);
                mma_16816(acc[1][2 * nq],     a1, b[0], b[2]);
                mma_16816(acc[1][2 * nq + 1], a1, b[1], b[3]);
            }
        }
        stC = (stC + 1 == 3) ? 0 : stC + 1;
    }
#undef LOAD_STAGE

    if (EPI == 0) {
        __half* out = sel_buf(5 + blockIdx.z);
        // Q gets the attention scale folded in here (2^-3, exact in fp16)
        const float osc = (blockIdx.z == 0) ? 0.125f : 1.0f;
#pragma unroll
        for (int mi = 0; mi < 2; mi++)
#pragma unroll
            for (int ni = 0; ni < 8; ni++) {
                int col = blockIdx.x * 128 + wn * 64 + ni * 8 + cq * 2;
                int h = col >> 6, dd = col & 63;
#pragma unroll
                for (int e2 = 0; e2 < 2; e2++) {
                    int row = blockIdx.y * 128 + wm * 32 + mi * 16 + r + e2 * 8;
                    int b = row >> 11, t = row & 2047;
                    __half2 hv = __floats2half2_rn(acc[mi][ni][e2 * 2] * osc,
                                                   acc[mi][ni][e2 * 2 + 1] * osc);
                    *reinterpret_cast<__half2*>(
                        &out[(((size_t)((b << 4) + h) * 2048) + t) * 64 + dd]) = hv;
                }
            }
    } else {
#pragma unroll
        for (int mi = 0; mi < 2; mi++)
#pragma unroll
            for (int ni = 0; ni < 8; ni++) {
                int col = blockIdx.x * 128 + wn * 64 + ni * 8 + cq * 2;
#pragma unroll
                for (int e2 = 0; e2 < 2; e2++) {
                    int row = blockIdx.y * 128 + wm * 32 + mi * 16 + r + e2 * 8;
                    *reinterpret_cast<float2*>(&outF[(size_t)row * 1024 + col]) =
                        make_float2(acc[mi][ni][e2 * 2], acc[mi][ni][e2 * 2 + 1]);
                }
            }
    }
}

// ---------------- Flash attention (R9 + prescaled Q): paired q-tiles, 2-stage -
// grid (16, 32), 256 threads. CTA i: q-tiles i (warps 0-3) and 31-i (warps 4-7).
// Smem: Q 2x9216 | K 2x9216 | V 2x9216 = 55296 B. 2 CTAs/SM.
// Q is pre-scaled by 2^-3 at the QKV epilogue, so logits = S - slope*(i-j).
constexpr uint32_t ATT_SMEM = 55296;

__global__ __launch_bounds__(256, 2) void k_attn() {
    extern __shared__ __align__(128) char asmem[];
    const uint32_t sb = smem_u32(asmem);

    const int bh = blockIdx.y;
    const int h = bh & 15;
    const __half* qp = g_q + (size_t)bh * Tc * Dc;
    const __half* kp = g_k + (size_t)bh * Tc * Dc;
    const __half* vp = g_v + (size_t)bh * Tc * Dc;

    const int ip = blockIdx.x;                 // pair index 0..15 (longest first)
    const int tid = threadIdx.x;
    const int lane = tid & 31, warp = tid >> 5;
    const int grp = warp >> 2;                 // 0 = low tile, 1 = high tile
    const int wl = warp & 3;
    const int r = lane >> 2, cq = lane & 3;

    const int qt = grp ? (31 - ip) : ip;
    const int q0 = qt * 64;
    const int njt = 32 - ip;                   // KV tiles streamed by this CTA
    const int myLast = grp ? (njt - 1) : ip;   // my diagonal tile index

    const float slope = exp2f(-0.5f * (float)(h + 1));
    const float NEG = -1e30f;

    const uint32_t qsb = sb + (uint32_t)grp * 9216;
    const uint32_t ksb0 = sb + 18432;
    const uint32_t vsb0 = sb + 36864;
    const int g = lane >> 3;
    const uint32_t qvoff = (uint32_t)(((g & 1) * 8 + (lane & 7)) * 144 + (g >> 1) * 16);
    const uint32_t koff = (uint32_t)((lane & 7) * 144 + g * 16);

    // load both Q tiles
#pragma unroll
    for (int i = 0; i < 4; i++) {
        int idx = tid + i * 256;
        int row = idx >> 3, c = idx & 7;       // row 0..127
        int tile = row >> 6, rin = row & 63;
        int qrow = (tile ? (31 - ip) : ip) * 64 + rin;
        *reinterpret_cast<uint4*>(asmem + tile * 9216 + rin * 144 + c * 16) =
            *reinterpret_cast<const uint4*>(qp + (size_t)qrow * 64 + c * 8);
    }
    // prefetch KV tile 0 into buffer 0
#pragma unroll
    for (int i = 0; i < 2; i++) {
        int idx = tid + i * 256;
        int row = idx >> 3, c = idx & 7;
        cp_async16(ksb0 + row * 144 + c * 16, kp + (size_t)row * 64 + c * 8);
        cp_async16(vsb0 + row * 144 + c * 16, vp + (size_t)row * 64 + c * 8);
    }
    cp_commit();
    cp_wait<0>();
    __syncthreads();

    // hoisted Q a-fragments (per warp, own tile)
    uint32_t aQ[4][4];
    {
        uint32_t qa = qsb + (uint32_t)(wl * 16 * 144) + qvoff;
#pragma unroll
        for (int kc = 0; kc < 4; kc++) ldsm_x4(aQ[kc], qa + kc * 32);
    }

    float m0 = NEG, m1 = NEG, l0 = 0.f, l1 = 0.f;
    float acc_o[8][4];
#pragma unroll
    for (int ni = 0; ni < 8; ni++)
#pragma unroll
        for (int e = 0; e < 4; e++) acc_o[ni][e] = 0.f;

    const int i0 = q0 + wl * 16 + r;

    for (int jt = 0; jt < njt; jt++) {
        if (jt > 0) {
            cp_wait<0>();
            __syncthreads();
        }
        if (jt + 1 < njt) {
            const int jn = (jt + 1) * 64;
            const uint32_t kb = ksb0 + ((jt + 1) & 1) * 9216;
            const uint32_t vb = vsb0 + ((jt + 1) & 1) * 9216;
#pragma unroll
            for (int i = 0; i < 2; i++) {
                int idx = tid + i * 256;
                int row = idx >> 3, c = idx & 7;
                cp_async16(kb + row * 144 + c * 16, kp + (size_t)(jn + row) * 64 + c * 8);
                cp_async16(vb + row * 144 + c * 16, vp + (size_t)(jn + row) * 64 + c * 8);
            }
            cp_commit();
        }

        if (jt <= myLast) {                    // group-uniform branch
            const uint32_t kb = ksb0 + (jt & 1) * 9216;
            const uint32_t vb = vsb0 + (jt & 1) * 9216;
            const int j0 = jt * 64;

            float s[8][4];
#pragma unroll
            for (int ni = 0; ni < 8; ni++)
#pragma unroll
                for (int e = 0; e < 4; e++) s[ni][e] = 0.f;
#pragma unroll
            for (int p = 0; p < 2; p++) {
#pragma unroll
                for (int ni = 0; ni < 8; ni++) {
                    uint32_t b[4];
                    ldsm_x4(b, kb + ni * 1152 + p * 64 + koff);
                    mma_16816(s[ni], aQ[2 * p], b[0], b[1]);
                    mma_16816(s[ni], aQ[2 * p + 1], b[2], b[3]);
                }
            }

            const bool diag = (jt == myLast);
            float rmax0 = NEG, rmax1 = NEG;
#pragma unroll
            for (int ni = 0; ni < 8; ni++) {
#pragma unroll
                for (int e = 0; e < 4; e++) {
                    int j = j0 + ni * 8 + cq * 2 + (e & 1);
                    int i = i0 + ((e >> 1) << 3);
                    // Q pre-scaled: logits = S - slope*(i-j)
                    float val = fmaf(-slope, (float)(i - j), s[ni][e]);
                    if (diag && j > i) val = NEG;
                    s[ni][e] = val;
                    if (e < 2) rmax0 = fmaxf(rmax0, val);
                    else       rmax1 = fmaxf(rmax1, val);
                }
            }
            rmax0 = fmaxf(rmax0, __shfl_xor_sync(0xffffffffu, rmax0, 1));
            rmax0 = fmaxf(rmax0, __shfl_xor_sync(0xffffffffu, rmax0, 2));
            rmax1 = fmaxf(rmax1, __shfl_xor_sync(0xffffffffu, rmax1, 1));
            rmax1 = fmaxf(rmax1, __shfl_xor_sync(0xffffffffu, rmax1, 2));

            float mn0 = fmaxf(m0, rmax0), mn1 = fmaxf(m1, rmax1);
            float al0 = __expf(m0 - mn0), al1 = __expf(m1 - mn1);

            float rs0 = 0.f, rs1 = 0.f;
#pragma unroll
            for (int ni = 0; ni < 8; ni++) {
#pragma unroll
                for (int e = 0; e < 4; e++) {
                    float p = __expf(s[ni][e] - ((e < 2) ? mn0 : mn1));
                    s[ni][e] = p;
                    if (e < 2) rs0 += p;
                    else       rs1 += p;
                }
            }
            rs0 += __shfl_xor_sync(0xffffffffu, rs0, 1);
            rs0 += __shfl_xor_sync(0xffffffffu, rs0, 2);
            rs1 += __shfl_xor_sync(0xffffffffu, rs1, 1);
            rs1 += __shfl_xor_sync(0xffffffffu, rs1, 2);

            l0 = l0 * al0 + rs0;
            l1 = l1 * al1 + rs1;
            m0 = mn0;
            m1 = mn1;

#pragma unroll
            for (int ni = 0; ni < 8; ni++) {
                acc_o[ni][0] *= al0; acc_o[ni][1] *= al0;
                acc_o[ni][2] *= al1; acc_o[ni][3] *= al1;
            }

#pragma unroll
            for (int kc = 0; kc < 4; kc++) {
                uint32_t pa[4];
                __half2 t0 = __floats2half2_rn(s[2 * kc][0], s[2 * kc][1]);
                __half2 t1 = __floats2half2_rn(s[2 * kc][2], s[2 * kc][3]);
                __half2 t2 = __floats2half2_rn(s[2 * kc + 1][0], s[2 * kc + 1][1]);
                __half2 t3 = __floats2half2_rn(s[2 * kc + 1][2], s[2 * kc + 1][3]);
                pa[0] = *reinterpret_cast<uint32_t*>(&t0);
                pa[1] = *reinterpret_cast<uint32_t*>(&t1);
                pa[2] = *reinterpret_cast<uint32_t*>(&t2);
                pa[3] = *reinterpret_cast<uint32_t*>(&t3);
#pragma unroll
                for (int nip = 0; nip < 4; nip++) {
                    uint32_t b[4];
                    ldsm_x4_t(b, vb + kc * 2304 + nip * 32 + qvoff);
                    mma_16816(acc_o[2 * nip], pa, b[0], b[1]);
                    mma_16816(acc_o[2 * nip + 1], pa, b[2], b[3]);
                }
            }
        }
    }

    // epilogue
    float il0 = 1.f / l0, il1 = 1.f / l1;
    int b = bh >> 4;
#pragma unroll
    for (int ni = 0; ni < 8; ni++) {
        int dd = ni * 8 + cq * 2;
        int col = h * 64 + dd;
        int t0r = q0 + wl * 16 + r;
        __half2 hv0 = __floats2half2_rn(acc_o[ni][0] * il0, acc_o[ni][1] * il0);
        __half2 hv1 = __floats2half2_rn(acc_o[ni][2] * il1, acc_o[ni][3] * il1);
        *reinterpret_cast<__half2*>(&g_attn[((size_t)b * 2048 + t0r) * 1024 + col]) = hv0;
        *reinterpret_cast<__half2*>(&g_attn[((size_t)b * 2048 + t0r + 8) * 1024 + col]) = hv1;
    }
}

// ---------------- launch ----------------
extern "C" void kernel_launch(void* const* d_in, const int* in_sizes, int n_in,
                              void* d_out, int out_size) {
    const float* x  = (const float*)d_in[0];
    const float* Wq = (const float*)d_in[1];
    const float* Wk = (const float*)d_in[2];
    const float* Wv = (const float*)d_in[3];
    const float* Wo = (const float*)d_in[4];
    float* out = (float*)d_out;

    static bool attr_done = false;
    if (!attr_done) {
        cudaFuncSetAttribute(k_gemm<0>, cudaFuncAttributeMaxDynamicSharedMemorySize, GEMM_SMEM);
        cudaFuncSetAttribute(k_gemm<1>, cudaFuncAttributeMaxDynamicSharedMemorySize, GEMM_SMEM);
        cudaFuncSetAttribute(k_attn, cudaFuncAttributeMaxDynamicSharedMemorySize, ATT_SMEM);
        attr_done = true;
    }

    k_cvt_all<<<2048, 256>>>(x, Wq, Wk, Wv, Wo);

    dim3 gq(Cc / 128, Mrows / 128, 3);    // fused QKV: (8, 32, 3) = 768 CTAs
    k_gemm<0><<<gq, 256, GEMM_SMEM>>>(nullptr);

    dim3 ga(16, BHc);                     // 512 CTAs, paired q-tiles
    k_attn<<<ga, 256, ATT_SMEM>>>();

    dim3 go(Cc / 128, Mrows / 128, 1);    // (8, 32) = 256 CTAs
    k_gemm<1><<<go, 256, GEMM_SMEM>>>(out);
}

// round 17
// speedup vs baseline: 1.0059x; 1.0059x over previous
#include <cuda_runtime.h>
#include <cuda_fp16.h>
#include <cstdint>

#define DI __device__ __forceinline__

// Problem sizes (fixed for this dataset)
constexpr int Bc = 2, Tc = 2048, Cc = 1024, Hc = 16, Dc = 64;
constexpr int Mrows = Bc * Tc;      // 4096
constexpr int BHc = Bc * Hc;        // 32
constexpr int Kdim = 1024;

// ---------------- static device scratch (no allocs allowed) ----------------
__device__ __align__(128) __half g_xh[Mrows * Cc];
__device__ __align__(128) __half g_wq[Cc * Cc], g_wk[Cc * Cc], g_wv[Cc * Cc], g_wo[Cc * Cc];
__device__ __align__(128) __half g_q[BHc * Tc * Dc], g_k[BHc * Tc * Dc], g_v[BHc * Tc * Dc];
__device__ __align__(128) __half g_attn[Mrows * Cc];

DI __half* sel_buf(int s) {
    switch (s) {
        case 0: return g_xh;
        case 1: return g_wq;
        case 2: return g_wk;
        case 3: return g_wv;
        case 4: return g_wo;
        case 5: return g_q;
        case 6: return g_k;
        case 7: return g_v;
        default: return g_attn;
    }
}

// ---------------- fused fp32 -> fp16 conversion, 4 float4/thread --------------
__global__ void k_cvt_all(const float* __restrict__ x, const float* __restrict__ wq,
                          const float* __restrict__ wk, const float* __restrict__ wv,
                          const float* __restrict__ wo) {
    int bid = blockIdx.x;
    const float* src;
    __half* dst;
    int base;
    if (bid < 1024) {
        src = x; dst = g_xh; base = bid * 1024;
    } else {
        int w = (bid - 1024) >> 8;            // 256 blocks per weight
        int lb = (bid - 1024) & 255;
        switch (w) {
            case 0: src = wq; dst = g_wq; break;
            case 1: src = wk; dst = g_wk; break;
            case 2: src = wv; dst = g_wv; break;
            default: src = wo; dst = g_wo; break;
        }
        base = lb * 1024;
    }
    float4 v[4];
#pragma unroll
    for (int j = 0; j < 4; j++)
        v[j] = reinterpret_cast<const float4*>(src)[base + threadIdx.x + j * 256];
#pragma unroll
    for (int j = 0; j < 4; j++) {
        __half2 h0 = __floats2half2_rn(v[j].x, v[j].y);
        __half2 h1 = __floats2half2_rn(v[j].z, v[j].w);
        uint2 pk;
        pk.x = *reinterpret_cast<uint32_t*>(&h0);
        pk.y = *reinterpret_cast<uint32_t*>(&h1);
        reinterpret_cast<uint2*>(dst)[base + threadIdx.x + j * 256] = pk;
    }
}

// ---------------- PTX helpers ----------------
DI uint32_t smem_u32(const void* p) {
    uint32_t a;
    asm("{ .reg .u64 t; cvta.to.shared.u64 t, %1; cvt.u32.u64 %0, t; }" : "=r"(a) : "l"(p));
    return a;
}
DI void cp_async16(uint32_t dst, const void* src) {
    asm volatile("cp.async.cg.shared.global [%0], [%1], 16;" :: "r"(dst), "l"(src) : "memory");
}
DI void cp_commit() { asm volatile("cp.async.commit_group;" ::: "memory"); }
template <int N> DI void cp_wait() { asm volatile("cp.async.wait_group %0;" :: "n"(N) : "memory"); }

DI void mma_16816(float* d, const uint32_t* a, uint32_t b0, uint32_t b1) {
    asm volatile(
        "mma.sync.aligned.m16n8k16.row.col.f32.f16.f16.f32 "
        "{%0,%1,%2,%3}, {%4,%5,%6,%7}, {%8,%9}, {%0,%1,%2,%3};\n"
        : "+f"(d[0]), "+f"(d[1]), "+f"(d[2]), "+f"(d[3])
        : "r"(a[0]), "r"(a[1]), "r"(a[2]), "r"(a[3]), "r"(b0), "r"(b1));
}
DI void ldsm_x4(uint32_t* r, uint32_t a) {
    asm volatile("ldmatrix.sync.aligned.m8n8.x4.shared.b16 {%0,%1,%2,%3}, [%4];"
                 : "=r"(r[0]), "=r"(r[1]), "=r"(r[2]), "=r"(r[3]) : "r"(a));
}
DI void ldsm_x4_t(uint32_t* r, uint32_t a) {
    asm volatile("ldmatrix.sync.aligned.m8n8.x4.trans.shared.b16 {%0,%1,%2,%3}, [%4];"
                 : "=r"(r[0]), "=r"(r[1]), "=r"(r[2]), "=r"(r[3]) : "r"(a));
}

// ---------------- GEMM v4 (frozen): 128x128 CTA, K-chunk 64, 3-stage ----------
constexpr uint32_t GSTG = 36864;
constexpr uint32_t GEMM_SMEM = 3 * GSTG;   // 110592

template <int EPI>
__global__ __launch_bounds__(256, 2) void k_gemm(float* __restrict__ outF) {
    extern __shared__ __align__(128) char smem[];
    const uint32_t sb = smem_u32(smem);

    const __half* A = (EPI == 0 ? g_xh : g_attn) + (size_t)blockIdx.y * 128 * Kdim;
    const __half* Bm = (EPI == 0 ? sel_buf(1 + blockIdx.z) : g_wo) + (size_t)blockIdx.x * 128 * Kdim;

    const int tid = threadIdx.x;
    const int lane = tid & 31, warp = tid >> 5;
    const int wm = warp >> 1, wn = warp & 1;
    const int r = lane >> 2, cq = lane & 3;
    const int g = lane >> 3;
    const uint32_t off16 = (uint32_t)(((g & 1) * 8 + (lane & 7)) * 144 + (g >> 1) * 16);

    const int lrow = tid >> 3, lc = tid & 7;

    float acc[2][8][4];
#pragma unroll
    for (int mi = 0; mi < 2; mi++)
#pragma unroll
        for (int ni = 0; ni < 8; ni++)
#pragma unroll
            for (int e = 0; e < 4; e++) acc[mi][ni][e] = 0.f;

#define LOAD_STAGE(KT_, ST_)                                                            \
    {                                                                                   \
        const int kt_ = (KT_);                                                          \
        const uint32_t sA = sb + (uint32_t)(ST_) * GSTG;                                \
        const uint32_t sB = sA + 18432;                                                 \
        _Pragma("unroll")                                                               \
        for (int i_ = 0; i_ < 4; i_++) {                                                \
            int row_ = lrow + i_ * 32;                                                  \
            cp_async16(sA + row_ * 144 + lc * 16, A + (size_t)row_ * Kdim + kt_ * 64 + lc * 8);  \
        }                                                                               \
        _Pragma("unroll")                                                               \
        for (int i_ = 0; i_ < 4; i_++) {                                                \
            int row_ = lrow + i_ * 32;                                                  \
            cp_async16(sB + row_ * 144 + lc * 16, Bm + (size_t)row_ * Kdim + kt_ * 64 + lc * 8); \
        }                                                                               \
    }

    LOAD_STAGE(0, 0); cp_commit();
    LOAD_STAGE(1, 1); cp_commit();

    constexpr int KT = Kdim / 64;   // 16
    int stC = 0;
    for (int kt = 0; kt < KT; kt++) {
        cp_wait<1>();
        __syncthreads();
        int stL = stC + 2; if (stL >= 3) stL -= 3;
        if (kt + 2 < KT) LOAD_STAGE(kt + 2, stL);
        cp_commit();

        const uint32_t sA = sb + (uint32_t)stC * GSTG;
        const uint32_t sB = sA + 18432;
#pragma unroll
        for (int kk = 0; kk < 4; kk++) {
            uint32_t a0[4], a1[4];
            ldsm_x4(a0, sA + (uint32_t)((wm * 32) * 144 + kk * 32) + off16);
            ldsm_x4(a1, sA + (uint32_t)((wm * 32 + 16) * 144 + kk * 32) + off16);
#pragma unroll
            for (int nq = 0; nq < 4; nq++) {
                uint32_t b[4];
                ldsm_x4(b, sB + (uint32_t)((wn * 64 + nq * 16) * 144 + kk * 32) + off16);
                mma_16816(acc[0][2 * nq],     a0, b[0], b[2]);
                mma_16816(acc[0][2 * nq + 1], a0, b[1], b[3]);
                mma_16816(acc[1][2 * nq],     a1, b[0], b[2]);
                mma_16816(acc[1][2 * nq + 1], a1, b[1], b[3]);
            }
        }
        stC = (stC + 1 == 3) ? 0 : stC + 1;
    }
#undef LOAD_STAGE

    if (EPI == 0) {
        __half* out = sel_buf(5 + blockIdx.z);
#pragma unroll
        for (int mi = 0; mi < 2; mi++)
#pragma unroll
            for (int ni = 0; ni < 8; ni++) {
                int col = blockIdx.x * 128 + wn * 64 + ni * 8 + cq * 2;
                int h = col >> 6, dd = col & 63;
#pragma unroll
                for (int e2 = 0; e2 < 2; e2++) {
                    int row = blockIdx.y * 128 + wm * 32 + mi * 16 + r + e2 * 8;
                    int b = row >> 11, t = row & 2047;
                    __half2 hv = __floats2half2_rn(acc[mi][ni][e2 * 2], acc[mi][ni][e2 * 2 + 1]);
                    *reinterpret_cast<__half2*>(
                        &out[(((size_t)((b << 4) + h) * 2048) + t) * 64 + dd]) = hv;
                }
            }
    } else {
#pragma unroll
        for (int mi = 0; mi < 2; mi++)
#pragma unroll
            for (int ni = 0; ni < 8; ni++) {
                int col = blockIdx.x * 128 + wn * 64 + ni * 8 + cq * 2;
#pragma unroll
                for (int e2 = 0; e2 < 2; e2++) {
                    int row = blockIdx.y * 128 + wm * 32 + mi * 16 + r + e2 * 8;
                    *reinterpret_cast<float2*>(&outF[(size_t)row * 1024 + col]) =
                        make_float2(acc[mi][ni][e2 * 2], acc[mi][ni][e2 * 2 + 1]);
                }
            }
    }
}

// ---------------- Flash attention (R9, terminal): paired q-tiles, 2-stage -----
// grid (16, 32), 256 threads. CTA i: q-tiles i (warps 0-3) and 31-i (warps 4-7).
// Smem: Q 2x9216 | K 2x9216 | V 2x9216 = 55296 B. 2 CTAs/SM.
constexpr uint32_t ATT_SMEM = 55296;

__global__ __launch_bounds__(256, 2) void k_attn() {
    extern __shared__ __align__(128) char asmem[];
    const uint32_t sb = smem_u32(asmem);

    const int bh = blockIdx.y;
    const int h = bh & 15;
    const __half* qp = g_q + (size_t)bh * Tc * Dc;
    const __half* kp = g_k + (size_t)bh * Tc * Dc;
    const __half* vp = g_v + (size_t)bh * Tc * Dc;

    const int ip = blockIdx.x;                 // pair index 0..15 (longest first)
    const int tid = threadIdx.x;
    const int lane = tid & 31, warp = tid >> 5;
    const int grp = warp >> 2;                 // 0 = low tile, 1 = high tile
    const int wl = warp & 3;
    const int r = lane >> 2, cq = lane & 3;

    const int qt = grp ? (31 - ip) : ip;
    const int q0 = qt * 64;
    const int njt = 32 - ip;                   // KV tiles streamed by this CTA
    const int myLast = grp ? (njt - 1) : ip;   // my diagonal tile index

    const float slope = exp2f(-0.5f * (float)(h + 1));
    const float scale = 0.125f;
    const float NEG = -1e30f;

    const uint32_t qsb = sb + (uint32_t)grp * 9216;
    const uint32_t ksb0 = sb + 18432;
    const uint32_t vsb0 = sb + 36864;
    const int g = lane >> 3;
    const uint32_t qvoff = (uint32_t)(((g & 1) * 8 + (lane & 7)) * 144 + (g >> 1) * 16);
    const uint32_t koff = (uint32_t)((lane & 7) * 144 + g * 16);

    // load both Q tiles
#pragma unroll
    for (int i = 0; i < 4; i++) {
        int idx = tid + i * 256;
        int row = idx >> 3, c = idx & 7;       // row 0..127
        int tile = row >> 6, rin = row & 63;
        int qrow = (tile ? (31 - ip) : ip) * 64 + rin;
        *reinterpret_cast<uint4*>(asmem + tile * 9216 + rin * 144 + c * 16) =
            *reinterpret_cast<const uint4*>(qp + (size_t)qrow * 64 + c * 8);
    }
    // prefetch KV tile 0 into buffer 0
#pragma unroll
    for (int i = 0; i < 2; i++) {
        int idx = tid + i * 256;
        int row = idx >> 3, c = idx & 7;
        cp_async16(ksb0 + row * 144 + c * 16, kp + (size_t)row * 64 + c * 8);
        cp_async16(vsb0 + row * 144 + c * 16, vp + (size_t)row * 64 + c * 8);
    }
    cp_commit();
    cp_wait<0>();
    __syncthreads();

    // hoisted Q a-fragments (per warp, own tile)
    uint32_t aQ[4][4];
    {
        uint32_t qa = qsb + (uint32_t)(wl * 16 * 144) + qvoff;
#pragma unroll
        for (int kc = 0; kc < 4; kc++) ldsm_x4(aQ[kc], qa + kc * 32);
    }

    float m0 = NEG, m1 = NEG, l0 = 0.f, l1 = 0.f;
    float acc_o[8][4];
#pragma unroll
    for (int ni = 0; ni < 8; ni++)
#pragma unroll
        for (int e = 0; e < 4; e++) acc_o[ni][e] = 0.f;

    const int i0 = q0 + wl * 16 + r;

    for (int jt = 0; jt < njt; jt++) {
        if (jt > 0) {
            cp_wait<0>();
            __syncthreads();
        }
        if (jt + 1 < njt) {
            const int jn = (jt + 1) * 64;
            const uint32_t kb = ksb0 + ((jt + 1) & 1) * 9216;
            const uint32_t vb = vsb0 + ((jt + 1) & 1) * 9216;
#pragma unroll
            for (int i = 0; i < 2; i++) {
                int idx = tid + i * 256;
                int row = idx >> 3, c = idx & 7;
                cp_async16(kb + row * 144 + c * 16, kp + (size_t)(jn + row) * 64 + c * 8);
                cp_async16(vb + row * 144 + c * 16, vp + (size_t)(jn + row) * 64 + c * 8);
            }
            cp_commit();
        }

        if (jt <= myLast) {                    // group-uniform branch
            const uint32_t kb = ksb0 + (jt & 1) * 9216;
            const uint32_t vb = vsb0 + (jt & 1) * 9216;
            const int j0 = jt * 64;

            float s[8][4];
#pragma unroll
            for (int ni = 0; ni < 8; ni++)
#pragma unroll
                for (int e = 0; e < 4; e++) s[ni][e] = 0.f;
#pragma unroll
            for (int p = 0; p < 2; p++) {
#pragma unroll
                for (int ni = 0; ni < 8; ni++) {
                    uint32_t b[4];
                    ldsm_x4(b, kb + ni * 1152 + p * 64 + koff);
                    mma_16816(s[ni], aQ[2 * p], b[0], b[1]);
                    mma_16816(s[ni], aQ[2 * p + 1], b[2], b[3]);
                }
            }

            const bool diag = (jt == myLast);
            float rmax0 = NEG, rmax1 = NEG;
#pragma unroll
            for (int ni = 0; ni < 8; ni++) {
#pragma unroll
                for (int e = 0; e < 4; e++) {
                    int j = j0 + ni * 8 + cq * 2 + (e & 1);
                    int i = i0 + ((e >> 1) << 3);
                    float val = s[ni][e] * scale - slope * (float)(i - j);
                    if (diag && j > i) val = NEG;
                    s[ni][e] = val;
                    if (e < 2) rmax0 = fmaxf(rmax0, val);
                    else       rmax1 = fmaxf(rmax1, val);
                }
            }
            rmax0 = fmaxf(rmax0, __shfl_xor_sync(0xffffffffu, rmax0, 1));
            rmax0 = fmaxf(rmax0, __shfl_xor_sync(0xffffffffu, rmax0, 2));
            rmax1 = fmaxf(rmax1, __shfl_xor_sync(0xffffffffu, rmax1, 1));
            rmax1 = fmaxf(rmax1, __shfl_xor_sync(0xffffffffu, rmax1, 2));

            float mn0 = fmaxf(m0, rmax0), mn1 = fmaxf(m1, rmax1);
            float al0 = __expf(m0 - mn0), al1 = __expf(m1 - mn1);

            float rs0 = 0.f, rs1 = 0.f;
#pragma unroll
            for (int ni = 0; ni < 8; ni++) {
#pragma unroll
                for (int e = 0; e < 4; e++) {
                    float p = __expf(s[ni][e] - ((e < 2) ? mn0 : mn1));
                    s[ni][e] = p;
                    if (e < 2) rs0 += p;
                    else       rs1 += p;
                }
            }
            rs0 += __shfl_xor_sync(0xffffffffu, rs0, 1);
            rs0 += __shfl_xor_sync(0xffffffffu, rs0, 2);
            rs1 += __shfl_xor_sync(0xffffffffu, rs1, 1);
            rs1 += __shfl_xor_sync(0xffffffffu, rs1, 2);

            l0 = l0 * al0 + rs0;
            l1 = l1 * al1 + rs1;
            m0 = mn0;
            m1 = mn1;

#pragma unroll
            for (int ni = 0; ni < 8; ni++) {
                acc_o[ni][0] *= al0; acc_o[ni][1] *= al0;
                acc_o[ni][2] *= al1; acc_o[ni][3] *= al1;
            }

#pragma unroll
            for (int kc = 0; kc < 4; kc++) {
                uint32_t pa[4];
                __half2 t0 = __floats2half2_rn(s[2 * kc][0], s[2 * kc][1]);
                __half2 t1 = __floats2half2_rn(s[2 * kc][2], s[2 * kc][3]);
                __half2 t2 = __floats2half2_rn(s[2 * kc + 1][0], s[2 * kc + 1][1]);
                __half2 t3 = __floats2half2_rn(s[2 * kc + 1][2], s[2 * kc + 1][3]);
                pa[0] = *reinterpret_cast<uint32_t*>(&t0);
                pa[1] = *reinterpret_cast<uint32_t*>(&t1);
                pa[2] = *reinterpret_cast<uint32_t*>(&t2);
                pa[3] = *reinterpret_cast<uint32_t*>(&t3);
#pragma unroll
                for (int nip = 0; nip < 4; nip++) {
                    uint32_t b[4];
                    ldsm_x4_t(b, vb + kc * 2304 + nip * 32 + qvoff);
                    mma_16816(acc_o[2 * nip], pa, b[0], b[1]);
                    mma_16816(acc_o[2 * nip + 1], pa, b[2], b[3]);
                }
            }
        }
    }

    // epilogue
    float il0 = 1.f / l0, il1 = 1.f / l1;
    int b = bh >> 4;
#pragma unroll
    for (int ni = 0; ni < 8; ni++) {
        int dd = ni * 8 + cq * 2;
        int col = h * 64 + dd;
        int t0r = q0 + wl * 16 + r;
        __half2 hv0 = __floats2half2_rn(acc_o[ni][0] * il0, acc_o[ni][1] * il0);
        __half2 hv1 = __floats2half2_rn(acc_o[ni][2] * il1, acc_o[ni][3] * il1);
        *reinterpret_cast<__half2*>(&g_attn[((size_t)b * 2048 + t0r) * 1024 + col]) = hv0;
        *reinterpret_cast<__half2*>(&g_attn[((size_t)b * 2048 + t0r + 8) * 1024 + col]) = hv1;
    }
}

// ---------------- launch ----------------
extern "C" void kernel_launch(void* const* d_in, const int* in_sizes, int n_in,
                              void* d_out, int out_size) {
    const float* x  = (const float*)d_in[0];
    const float* Wq = (const float*)d_in[1];
    const float* Wk = (const float*)d_in[2];
    const float* Wv = (const float*)d_in[3];
    const float* Wo = (const float*)d_in[4];
    float* out = (float*)d_out;

    static bool attr_done = false;
    if (!attr_done) {
        cudaFuncSetAttribute(k_gemm<0>, cudaFuncAttributeMaxDynamicSharedMemorySize, GEMM_SMEM);
        cudaFuncSetAttribute(k_gemm<1>, cudaFuncAttributeMaxDynamicSharedMemorySize, GEMM_SMEM);
        cudaFuncSetAttribute(k_attn, cudaFuncAttributeMaxDynamicSharedMemorySize, ATT_SMEM);
        attr_done = true;
    }

    k_cvt_all<<<2048, 256>>>(x, Wq, Wk, Wv, Wo);

    dim3 gq(Cc / 128, Mrows / 128, 3);    // fused QKV: (8, 32, 3) = 768 CTAs
    k_gemm<0><<<gq, 256, GEMM_SMEM>>>(nullptr);

    dim3 ga(16, BHc);                     // 512 CTAs, paired q-tiles
    k_attn<<<ga, 256, ATT_SMEM>>>();

    dim3 go(Cc / 128, Mrows / 128, 1);    // (8, 32) = 256 CTAs
    k_gemm<1><<<go, 256, GEMM_SMEM>>>(out);
}